// round 14
// baseline (speedup 1.0000x reference)
#include <cuda_runtime.h>
#include <cuda_fp16.h>
#include <cstdint>
#include <cstddef>

#define N_    128
#define CIN   8
#define HIN   128
#define WIN   128
#define COUT  64
#define OH    126
#define OW    126
#define G_    16
#define OPH   31
#define OPW   31

#define HB_   16
#define WB_   4
#define NT    4      // h-tiles per block
#define NTILES (N_ * HB_ * WB_)

// ---- smem layout (bytes) ----
// resident: sB2 [0,10240) — NOT aliased (must survive all tiles)
// phase 1:  sX  [10240,23200)  (9 ic planes x 10 x 36, plane 8 zeros)
// phase 2:  sO  [10240,86016)  (256 px x 74 floats) — sX aliases sO's front
#define OFF_B2   0
#define OFF_X    10240
#define OFF_OUT  10240
#define OFF_CB   86016
#define OFF_RED  86272
#define OFF_SG   88320
#define SMEM_TOTAL 88576

#define SO 74    // s_out px stride

// ---- device scratch ----
// B pairs: [oc][kk(5)][r4(4)] uint2 = (half2(k0,k0+1), half2(k0+8,k0+9)), k0=16kk+2r4
__device__ uint2 g_B2h[64 * 20];
__device__ float g_sgn[64];
__device__ float g_ext[(size_t)N_ * COUT * OPH * OPW];
__device__ float g_ps[NTILES * G_];
__device__ float g_pq[NTILES * G_];
__device__ float g_mean[N_ * G_];
__device__ float g_rsig[N_ * G_];

__device__ __forceinline__ uint32_t pack_h2(float lo, float hi) {
    uint32_t r;
    asm("cvt.rn.f16x2.f32 %0, %1, %2;" : "=r"(r) : "f"(hi), "f"(lo));
    return r;
}

__device__ __forceinline__ void mma16(float* c, const uint32_t* a, uint32_t b0, uint32_t b1) {
    asm volatile(
        "mma.sync.aligned.m16n8k16.row.col.f32.f16.f16.f32 "
        "{%0,%1,%2,%3}, {%4,%5,%6,%7}, {%8,%9}, {%0,%1,%2,%3};"
        : "+f"(c[0]), "+f"(c[1]), "+f"(c[2]), "+f"(c[3])
        : "r"(a[0]), "r"(a[1]), "r"(a[2]), "r"(a[3]), "r"(b0), "r"(b1));
}

// k (< 80) -> sX offset ic*360 + kh*36 + kw   (sX layout [ic(9)][10][36])
__device__ __forceinline__ int koff(int k) {
    int ic = (k * 57) >> 9;
    int r  = k - 9 * ic;
    int kh = (r * 11) >> 5;
    int kw = r - 3 * kh;
    return ic * 360 + kh * 36 + kw;
}

// ---------------------------------------------------------------------------
// Kernel 0: weights -> fp16 pairs keyed [oc][kk][r4]; sign of a per oc.
// ---------------------------------------------------------------------------
__global__ void bprep_kernel(const float* __restrict__ cw,
                             const float* __restrict__ gnw,
                             const float* __restrict__ scale)
{
    int e = blockIdx.x * blockDim.x + threadIdx.x;
    if (e < 64) g_sgn[e] = (gnw[e] * scale[e] > 0.f) ? 1.f : -1.f;
    if (e >= 64 * 20) return;
    int oc = e / 20, rem = e - (e / 20) * 20;
    int kk = rem >> 2, r4 = rem & 3;
    int k0 = 16 * kk + 2 * r4;

    float w[4];
    #pragma unroll
    for (int i = 0; i < 4; ++i) {
        int k = k0 + ((i >> 1) << 3) + (i & 1);
        float v = 0.f;
        if (k < 72) {
            int ic = k / 9, r = k % 9;
            v = cw[((oc * 8 + ic) * 3 + r / 3) * 3 + (r % 3)];
        }
        w[i] = v;
    }
    __half2 p0 = __floats2half2_rn(w[0], w[1]);
    __half2 p1 = __floats2half2_rn(w[2], w[3]);
    uint2 out;
    out.x = *(uint32_t*)&p0;
    out.y = *(uint32_t*)&p1;
    g_B2h[e] = out;
}

// ---------------------------------------------------------------------------
// Kernel 1: implicit-GEMM conv (mma.sync fp16, f32 accum) + fused pool
// extreme + per-group partials. FOUR h-tiles per block with rolling register
// prefetch of the next tile's input during the current tile's compute.
// 256 threads, grid (wb, hb4, n) with hb = 4*hb4 + it.
// ---------------------------------------------------------------------------
__global__ __launch_bounds__(256, 2)
void conv_mma_kernel(const float* __restrict__ x, const float* __restrict__ cb)
{
    extern __shared__ char smem[];
    uint2*  sB2 = (uint2*)(smem + OFF_B2);    // [oc][kk][r4], stride 20/oc (resident)
    float*  sX  = (float*)(smem + OFF_X);     // [9][10][36], plane 8 zeroed
    float*  sO  = (float*)(smem + OFF_OUT);   // [256][SO]
    float*  sCb = (float*)(smem + OFF_CB);
    float*  sRd = (float*)(smem + OFF_RED);
    float*  sSg = (float*)(smem + OFF_SG);

    const int tid  = threadIdx.x;
    const int wid  = tid >> 5;
    const int lane = tid & 31;
    const int wb = blockIdx.x, hb4 = blockIdx.y, n = blockIdx.z;
    const int w0 = wb * 32;

    const int q  = lane >> 2;
    const int r4 = lane & 3;

    // copy packed weights once per block (640 float4) — survives all tiles
    {
        const float4* src = (const float4*)g_B2h;
        float4* dst = (float4*)sB2;
        #pragma unroll 3
        for (int i = tid; i < 640; i += 256) dst[i] = src[i];
    }
    if (tid < 64) { sCb[tid] = cb[tid]; sSg[tid] = g_sgn[tid]; }

    // per-thread staging coordinates (4 chunks of 256 cover 810 float4 slots)
    int s_ic[4], s_hr[4], s_c4[4];
    #pragma unroll
    for (int i = 0; i < 4; ++i) {
        int idx = tid + (i << 8);
        s_ic[i] = idx / 90;
        int rem = idx - s_ic[i] * 90;
        s_hr[i] = rem / 9;
        s_c4[i] = rem - s_hr[i] * 9;
    }

    // ---- stage tile 0 ----
    {
        const int h0 = (hb4 * NT) * 8;
        #pragma unroll
        for (int i = 0; i < 4; ++i) {
            int idx = tid + (i << 8);
            if (idx >= 810) break;
            int ic = s_ic[i], h = h0 + s_hr[i], gw = w0 + s_c4[i] * 4;
            float4 v = make_float4(0.f, 0.f, 0.f, 0.f);
            if (ic < CIN && h < HIN) {
                const float* rp = x + (((size_t)n * CIN + ic) * HIN + h) * WIN;
                if (gw + 3 < WIN) v = *(const float4*)(rp + gw);
                else {
                    if (gw + 0 < WIN) v.x = rp[gw + 0];
                    if (gw + 1 < WIN) v.y = rp[gw + 1];
                    if (gw + 2 < WIN) v.z = rp[gw + 2];
                }
            }
            *(float4*)(sX + (ic * 10 + s_hr[i]) * 36 + s_c4[i] * 4) = v;
        }
    }
    __syncthreads();

    const int P = wid * 36 + 4 * q;
    float4 pf[4];   // rolling register prefetch buffer

    for (int it = 0; it < NT; ++it) {
        const int hb = hb4 * NT + it;
        const int h0 = hb * 8;

        // prefetch next tile's input into registers (overlaps this tile's MMA)
        if (it < NT - 1) {
            const int h1 = (hb + 1) * 8;
            #pragma unroll
            for (int i = 0; i < 4; ++i) {
                int idx = tid + (i << 8);
                float4 v = make_float4(0.f, 0.f, 0.f, 0.f);
                int ic = s_ic[i], h = h1 + s_hr[i], gw = w0 + s_c4[i] * 4;
                if (idx < 810 && ic < CIN && h < HIN) {
                    const float* rp = x + (((size_t)n * CIN + ic) * HIN + h) * WIN;
                    if (gw + 3 < WIN) v = *(const float4*)(rp + gw);
                    else {
                        if (gw + 0 < WIN) v.x = rp[gw + 0];
                        if (gw + 1 < WIN) v.y = rp[gw + 1];
                        if (gw + 2 < WIN) v.z = rp[gw + 2];
                    }
                }
                pf[i] = v;
            }
        }

        // ---- MMA mainloop: 5 k16-steps (K padded 72 -> 80) ----
        float acc[2][8][4];
        #pragma unroll
        for (int t = 0; t < 2; ++t)
            #pragma unroll
            for (int j = 0; j < 8; ++j)
                #pragma unroll
                for (int u = 0; u < 4; ++u) acc[t][j][u] = 0.f;

        #pragma unroll
        for (int kk = 0; kk < 5; ++kk) {
            const int k0 = 16 * kk + 2 * r4;
            const float* p00 = sX + koff(k0)     + P;
            const float* p01 = sX + koff(k0 + 1) + P;
            const float* p10 = sX + koff(k0 + 8) + P;
            const float* p11 = sX + koff(k0 + 9) + P;

            uint32_t a[2][4];
            #pragma unroll
            for (int t = 0; t < 2; ++t) {
                const int c = 2 * t;
                a[t][0] = pack_h2(p00[c],     p01[c]);
                a[t][1] = pack_h2(p00[c + 1], p01[c + 1]);
                a[t][2] = pack_h2(p10[c],     p11[c]);
                a[t][3] = pack_h2(p10[c + 1], p11[c + 1]);
            }
            const uint2* bp = sB2 + q * 20 + kk * 4 + r4;
            #pragma unroll
            for (int j = 0; j < 8; ++j) {
                uint2 bv = bp[j * 160];
                mma16(acc[0][j], a[0], bv.x, bv.y);
                mma16(acc[1][j], a[1], bv.x, bv.y);
            }
        }
        __syncthreads();   // sX dead; region becomes part of sO

        // ---- epilogue: +bias, zero invalid, paired STS.64 -> sO[px][oc] ----
        const bool hok = (h0 + wid) < OH;
        #pragma unroll
        for (int t = 0; t < 2; ++t) {
            const int ww0 = 4 * q + 2 * t;
            const int px  = (wid << 5) + ww0;
            const bool v0 = hok && (w0 + ww0 < OW);
            const bool v1 = hok && (w0 + ww0 + 1 < OW);
            #pragma unroll
            for (int j = 0; j < 8; ++j) {
                const int oc = (j << 3) + (r4 << 1);
                float2 bc = *(float2*)(sCb + oc);
                float2 e0, e1;
                e0.x = v0 ? acc[t][j][0] + bc.x : 0.f;
                e0.y = v0 ? acc[t][j][1] + bc.y : 0.f;
                e1.x = v1 ? acc[t][j][2] + bc.x : 0.f;
                e1.y = v1 ? acc[t][j][3] + bc.y : 0.f;
                *(float2*)(sO + px * SO + oc)       = e0;
                *(float2*)(sO + (px + 1) * SO + oc) = e1;
            }
        }
        __syncthreads();

        // ---- stats: column scan, 4 partials per oc, fixed order ----
        {
            const int oc = tid & 63, part = tid >> 6;
            const float* p = sO + part * 64 * SO + oc;
            float s = 0.f, qq = 0.f;
            #pragma unroll 8
            for (int i = 0; i < 64; ++i) {
                float v = p[i * SO];
                s += v; qq = fmaf(v, v, qq);
            }
            sRd[tid] = s; sRd[256 + tid] = qq;
        }
        __syncthreads();

        const int tile = (n * HB_ + hb) * WB_ + wb;
        if (tid < 16) {
            float S = 0.f, Q = 0.f;
            #pragma unroll
            for (int part = 0; part < 4; ++part)
                #pragma unroll
                for (int c2 = 0; c2 < 4; ++c2) {
                    S += sRd[part * 64 + tid * 4 + c2];
                    Q += sRd[256 + part * 64 + tid * 4 + c2];
                }
            g_ps[tile * G_ + tid] = S;
            g_pq[tile * G_ + tid] = Q;
        }

        // ---- pool: sign-relevant extreme only ----
        #pragma unroll
        for (int i = 0; i < 4; ++i) {
            const int task = tid + (i << 8);
            const int oc = task & 63, j = (task >> 6) & 7, prl = task >> 9;
            const int pw = wb * 8 + j, pr = hb * 2 + prl;
            if (pw < OPW && pr < OPH) {
                float mx = -3.4e38f, mn = 3.4e38f;
                #pragma unroll
                for (int a2 = 0; a2 < 4; ++a2)
                    #pragma unroll
                    for (int b2 = 0; b2 < 4; ++b2) {
                        float v = sO[((prl * 4 + a2) * 32 + j * 4 + b2) * SO + oc];
                        mx = fmaxf(mx, v); mn = fminf(mn, v);
                    }
                size_t o = ((size_t)(n * COUT + oc) * OPH + pr) * OPW + pw;
                g_ext[o] = (sSg[oc] > 0.f) ? mx : mn;
            }
        }

        // ---- commit prefetched tile into sX (after sO reads complete) ----
        if (it < NT - 1) {
            __syncthreads();   // pool/stats reads of sO done; sX region reusable
            #pragma unroll
            for (int i = 0; i < 4; ++i) {
                int idx = tid + (i << 8);
                if (idx < 810)
                    *(float4*)(sX + (s_ic[i] * 10 + s_hr[i]) * 36 + s_c4[i] * 4) = pf[i];
            }
            __syncthreads();
        }
    }
}

// ---------------------------------------------------------------------------
// Kernel 2: reduce per-tile partials -> mean, rsig. One warp per (n,g),
// fixed shuffle tree (deterministic).
// ---------------------------------------------------------------------------
__global__ __launch_bounds__(256) void stats_reduce_kernel()
{
    const int wg   = (blockIdx.x * 256 + threadIdx.x) >> 5;
    const int lane = threadIdx.x & 31;
    if (wg >= N_ * G_) return;
    const int n = wg / G_, g = wg - n * G_;

    const int base = n * HB_ * WB_;   // 64 tiles per n
    float S = g_ps[(base + lane) * G_ + g] + g_ps[(base + 32 + lane) * G_ + g];
    float Q = g_pq[(base + lane) * G_ + g] + g_pq[(base + 32 + lane) * G_ + g];
    #pragma unroll
    for (int m = 16; m > 0; m >>= 1) {
        S += __shfl_xor_sync(0xFFFFFFFF, S, m);
        Q += __shfl_xor_sync(0xFFFFFFFF, Q, m);
    }
    if (lane == 0) {
        const float inv_cnt = 1.f / (float)(4 * OH * OW);
        float mean = S * inv_cnt;
        float var  = Q * inv_cnt - mean * mean;
        g_mean[wg] = mean;
        g_rsig[wg] = rsqrtf(var + 1e-5f);
    }
}

// ---------------------------------------------------------------------------
// Kernel 3: affine on pre-selected extreme, clamp. 4 px / thread (float4).
// ---------------------------------------------------------------------------
__global__ __launch_bounds__(256) void finalize_pool_kernel(
    const float* __restrict__ gnw,
    const float* __restrict__ gnb,
    const float* __restrict__ scale,
    float* __restrict__ out)
{
    const int total4 = (N_ * COUT * OPH * OPW) >> 2;
    int t4 = blockIdx.x * 256 + threadIdx.x;
    if (t4 >= total4) return;
    int idx = t4 << 2;

    float4 e = *(const float4*)(g_ext + idx);
    float r[4] = {e.x, e.y, e.z, e.w};
    float4 o;
    float* op = &o.x;

    #pragma unroll
    for (int i = 0; i < 4; ++i) {
        int id = idx + i;
        int t = id / (OPH * OPW);
        int c = t % COUT;
        int n = t / COUT;
        int gi = n * G_ + (c >> 2);
        float mean = g_mean[gi];
        float rsig = g_rsig[gi];
        float a = rsig * gnw[c] * scale[c];
        float b = (gnb[c] - mean * rsig * gnw[c]) * scale[c];
        op[i] = fminf(fmaxf(fmaf(r[i], a, b), 0.f), 1.f);
    }
    *(float4*)(out + idx) = o;
}

// ---------------------------------------------------------------------------
extern "C" void kernel_launch(void* const* d_in, const int* in_sizes, int n_in,
                              void* d_out, int out_size)
{
    const float* x     = (const float*)d_in[0];
    const float* cw    = (const float*)d_in[1];
    const float* cb    = (const float*)d_in[2];
    const float* gnw   = (const float*)d_in[3];
    const float* gnb   = (const float*)d_in[4];
    const float* scale = (const float*)d_in[5];
    float* out = (float*)d_out;

    static bool attr_set = false;
    if (!attr_set) {
        cudaFuncSetAttribute(conv_mma_kernel,
                             cudaFuncAttributeMaxDynamicSharedMemorySize, SMEM_TOTAL);
        attr_set = true;
    }

    bprep_kernel<<<6, 256>>>(cw, gnw, scale);

    dim3 grid(WB_, HB_ / NT, N_);
    conv_mma_kernel<<<grid, 256, SMEM_TOTAL>>>(x, cb);

    stats_reduce_kernel<<<(N_ * G_ * 32 + 255) / 256, 256>>>();

    const int total4 = (N_ * COUT * OPH * OPW) / 4;
    finalize_pool_kernel<<<(total4 + 255) / 256, 256>>>(gnw, gnb, scale, out);
}

// round 15
// speedup vs baseline: 1.6442x; 1.6442x over previous
#include <cuda_runtime.h>
#include <cuda_fp16.h>
#include <cstdint>
#include <cstddef>

#define N_    128
#define CIN   8
#define HIN   128
#define WIN   128
#define COUT  64
#define OH    126
#define OW    126
#define G_    16
#define OPH   31
#define OPW   31

#define HB_   16
#define WB_   4
#define NTILES (N_ * HB_ * WB_)

// ---- smem layout (bytes) — NO aliasing ----
#define OFF_B2   0        // 64*20*8      = 10240
#define OFF_X    10240    // 9*10*36*4    = 12960 -> 23200
#define OFF_POOL 23200    // 8*8*72*4     = 18432 -> 41632 (row x win x oc, oc-stride 72)
#define OFF_SW   41632    // 8*16*8       = 1024  -> 42656 (warp group partials, float2)
#define OFF_CB   42656    // 256
#define OFF_SG   42912    // 256
#define SMEM_TOTAL 43168

// ---- device scratch ----
__device__ uint2 g_B2h[64 * 20];
__device__ float g_sgn[64];
__device__ float g_ext[(size_t)N_ * COUT * OPH * OPW];
__device__ float g_ps[NTILES * G_];
__device__ float g_pq[NTILES * G_];
__device__ float g_mean[N_ * G_];
__device__ float g_rsig[N_ * G_];

__device__ __forceinline__ uint32_t pack_h2(float lo, float hi) {
    uint32_t r;
    asm("cvt.rn.f16x2.f32 %0, %1, %2;" : "=r"(r) : "f"(hi), "f"(lo));
    return r;
}

__device__ __forceinline__ void mma16(float* c, const uint32_t* a, uint32_t b0, uint32_t b1) {
    asm volatile(
        "mma.sync.aligned.m16n8k16.row.col.f32.f16.f16.f32 "
        "{%0,%1,%2,%3}, {%4,%5,%6,%7}, {%8,%9}, {%0,%1,%2,%3};"
        : "+f"(c[0]), "+f"(c[1]), "+f"(c[2]), "+f"(c[3])
        : "r"(a[0]), "r"(a[1]), "r"(a[2]), "r"(a[3]), "r"(b0), "r"(b1));
}

__device__ __forceinline__ int koff(int k) {
    int ic = (k * 57) >> 9;
    int r  = k - 9 * ic;
    int kh = (r * 11) >> 5;
    int kw = r - 3 * kh;
    return ic * 360 + kh * 36 + kw;
}

// ---------------------------------------------------------------------------
// Kernel 0: weights -> fp16 pairs keyed [oc][kk][r4]; sign of a per oc.
// ---------------------------------------------------------------------------
__global__ void bprep_kernel(const float* __restrict__ cw,
                             const float* __restrict__ gnw,
                             const float* __restrict__ scale)
{
    int e = blockIdx.x * blockDim.x + threadIdx.x;
    if (e < 64) g_sgn[e] = (gnw[e] * scale[e] > 0.f) ? 1.f : -1.f;
    if (e >= 64 * 20) return;
    int oc = e / 20, rem = e - (e / 20) * 20;
    int kk = rem >> 2, r4 = rem & 3;
    int k0 = 16 * kk + 2 * r4;

    float w[4];
    #pragma unroll
    for (int i = 0; i < 4; ++i) {
        int k = k0 + ((i >> 1) << 3) + (i & 1);
        float v = 0.f;
        if (k < 72) {
            int ic = k / 9, r = k % 9;
            v = cw[((oc * 8 + ic) * 3 + r / 3) * 3 + (r % 3)];
        }
        w[i] = v;
    }
    __half2 p0 = __floats2half2_rn(w[0], w[1]);
    __half2 p1 = __floats2half2_rn(w[2], w[3]);
    uint2 out;
    out.x = *(uint32_t*)&p0;
    out.y = *(uint32_t*)&p1;
    g_B2h[e] = out;
}

// ---------------------------------------------------------------------------
// Kernel 1: implicit-GEMM conv (mma.sync fp16, f32 accum); pool + stats
// computed FROM REGISTERS (no s_out round-trip). Two h-tiles per block with
// register prefetch. 256 threads, grid (wb, hb2, n).
// ---------------------------------------------------------------------------
__global__ __launch_bounds__(256, 2)
void conv_mma_kernel(const float* __restrict__ x, const float* __restrict__ cb)
{
    extern __shared__ char smem[];
    uint2*  sB2    = (uint2*)(smem + OFF_B2);
    float*  sX     = (float*)(smem + OFF_X);
    float*  sPoolF = (float*)(smem + OFF_POOL);   // [row8][win8][oc72]
    float2* sPool2 = (float2*)(smem + OFF_POOL);
    float2* sW     = (float2*)(smem + OFF_SW);    // [warp8][group16]
    float*  sCb    = (float*)(smem + OFF_CB);
    float*  sSg    = (float*)(smem + OFF_SG);

    const int tid  = threadIdx.x;
    const int wid  = tid >> 5;
    const int lane = tid & 31;
    const int wb = blockIdx.x, hb2 = blockIdx.y, n = blockIdx.z;
    const int w0 = wb * 32;

    const int q  = lane >> 2;
    const int r4 = lane & 3;

    // packed weights (640 float4), bias, signs
    {
        const float4* src = (const float4*)g_B2h;
        float4* dst = (float4*)sB2;
        #pragma unroll 3
        for (int i = tid; i < 640; i += 256) dst[i] = src[i];
    }
    if (tid < 64) { sCb[tid] = cb[tid]; sSg[tid] = g_sgn[tid]; }

    // per-thread staging coordinates
    int s_ic[4], s_hr[4], s_c4[4];
    #pragma unroll
    for (int i = 0; i < 4; ++i) {
        int idx = tid + (i << 8);
        s_ic[i] = idx / 90;
        int rem = idx - s_ic[i] * 90;
        s_hr[i] = rem / 9;
        s_c4[i] = rem - s_hr[i] * 9;
    }

    // ---- stage tile 0 ----
    {
        const int h0 = (hb2 * 2) * 8;
        #pragma unroll
        for (int i = 0; i < 4; ++i) {
            int idx = tid + (i << 8);
            if (idx >= 810) break;
            int ic = s_ic[i], h = h0 + s_hr[i], gw = w0 + s_c4[i] * 4;
            float4 v = make_float4(0.f, 0.f, 0.f, 0.f);
            if (ic < CIN && h < HIN) {
                const float* rp = x + (((size_t)n * CIN + ic) * HIN + h) * WIN;
                if (gw + 3 < WIN) v = *(const float4*)(rp + gw);
                else {
                    if (gw + 0 < WIN) v.x = rp[gw + 0];
                    if (gw + 1 < WIN) v.y = rp[gw + 1];
                    if (gw + 2 < WIN) v.z = rp[gw + 2];
                }
            }
            *(float4*)(sX + (ic * 10 + s_hr[i]) * 36 + s_c4[i] * 4) = v;
        }
    }
    __syncthreads();

    const int P = wid * 36 + 4 * q;
    const int pxg = w0 + 4 * q;            // global w of this thread's window
    float4 pf[4];

    #pragma unroll
    for (int it = 0; it < 2; ++it) {
        const int hb = hb2 * 2 + it;
        const int h0 = hb * 8;

        // prefetch tile 1 input (overlaps tile 0 MMA)
        if (it == 0) {
            const int h1 = (hb2 * 2 + 1) * 8;
            #pragma unroll
            for (int i = 0; i < 4; ++i) {
                int idx = tid + (i << 8);
                float4 v = make_float4(0.f, 0.f, 0.f, 0.f);
                int ic = s_ic[i], h = h1 + s_hr[i], gw = w0 + s_c4[i] * 4;
                if (idx < 810 && ic < CIN && h < HIN) {
                    const float* rp = x + (((size_t)n * CIN + ic) * HIN + h) * WIN;
                    if (gw + 3 < WIN) v = *(const float4*)(rp + gw);
                    else {
                        if (gw + 0 < WIN) v.x = rp[gw + 0];
                        if (gw + 1 < WIN) v.y = rp[gw + 1];
                        if (gw + 2 < WIN) v.z = rp[gw + 2];
                    }
                }
                pf[i] = v;
            }
        }

        // ---- MMA mainloop: 5 k16-steps ----
        float acc[2][8][4];
        #pragma unroll
        for (int t = 0; t < 2; ++t)
            #pragma unroll
            for (int j = 0; j < 8; ++j)
                #pragma unroll
                for (int u = 0; u < 4; ++u) acc[t][j][u] = 0.f;

        #pragma unroll
        for (int kk = 0; kk < 5; ++kk) {
            const int k0 = 16 * kk + 2 * r4;
            const float* p00 = sX + koff(k0)     + P;
            const float* p01 = sX + koff(k0 + 1) + P;
            const float* p10 = sX + koff(k0 + 8) + P;
            const float* p11 = sX + koff(k0 + 9) + P;

            uint32_t a[2][4];
            #pragma unroll
            for (int t = 0; t < 2; ++t) {
                const int c = 2 * t;
                a[t][0] = pack_h2(p00[c],     p01[c]);
                a[t][1] = pack_h2(p00[c + 1], p01[c + 1]);
                a[t][2] = pack_h2(p10[c],     p11[c]);
                a[t][3] = pack_h2(p10[c + 1], p11[c + 1]);
            }
            const uint2* bp = sB2 + q * 20 + kk * 4 + r4;
            #pragma unroll
            for (int j = 0; j < 8; ++j) {
                uint2 bv = bp[j * 160];
                mma16(acc[0][j], a[0], bv.x, bv.y);
                mma16(acc[1][j], a[1], bv.x, bv.y);
            }
        }
        __syncthreads();   // all MMA reads of sX complete

        // commit prefetched tile 1 into sX now (consumed after next sync)
        if (it == 0) {
            #pragma unroll
            for (int i = 0; i < 4; ++i) {
                int idx = tid + (i << 8);
                if (idx < 810)
                    *(float4*)(sX + (s_ic[i] * 10 + s_hr[i]) * 36 + s_c4[i] * 4) = pf[i];
            }
        }

        // ---- phase 1: pool extremes + group partials from registers ----
        const bool hok = (h0 + wid) < OH;
        const bool c0 = hok && (pxg     < OW);
        const bool c1 = hok && (pxg + 1 < OW);
        const bool c2 = hok && (pxg + 2 < OW);
        const bool c3 = hok && (pxg + 3 < OW);
        float2* rowp = sPool2 + (wid * 8 + q) * 36;

        float s[8], qq[8];
        #pragma unroll
        for (int j = 0; j < 8; ++j) {
            const int oc = (j << 3) + (r4 << 1);
            float b0 = sCb[oc], b1 = sCb[oc + 1];
            // px 4q..4q+3 for oc (a0x) and oc+1 (a1x)
            float a00 = acc[0][j][0] + b0, a01 = acc[0][j][2] + b0;
            float a02 = acc[1][j][0] + b0, a03 = acc[1][j][2] + b0;
            float a10 = acc[0][j][1] + b1, a11 = acc[0][j][3] + b1;
            float a12 = acc[1][j][1] + b1, a13 = acc[1][j][3] + b1;

            // w-direction pooled extreme (only valid windows are read later)
            float mx0 = fmaxf(fmaxf(a00, a01), fmaxf(a02, a03));
            float mn0 = fminf(fminf(a00, a01), fminf(a02, a03));
            float mx1 = fmaxf(fmaxf(a10, a11), fmaxf(a12, a13));
            float mn1 = fminf(fminf(a10, a11), fminf(a12, a13));
            float e0 = (sSg[oc]     > 0.f) ? mx0 : mn0;
            float e1 = (sSg[oc + 1] > 0.f) ? mx1 : mn1;
            rowp[(j << 2) + r4] = make_float2(e0, e1);

            // stats (validity-zeroed)
            float v00 = c0 ? a00 : 0.f, v01 = c1 ? a01 : 0.f;
            float v02 = c2 ? a02 : 0.f, v03 = c3 ? a03 : 0.f;
            float v10 = c0 ? a10 : 0.f, v11 = c1 ? a11 : 0.f;
            float v12 = c2 ? a12 : 0.f, v13 = c3 ? a13 : 0.f;
            s[j] = ((v00 + v01) + (v02 + v03)) + ((v10 + v11) + (v12 + v13));
            qq[j] = fmaf(v00, v00, fmaf(v01, v01, fmaf(v02, v02, fmaf(v03, v03,
                    fmaf(v10, v10, fmaf(v11, v11, fmaf(v12, v12, v13 * v13)))))));
        }

        // warp shuffle reduce over coset {1,4,8,16} (fixed tree, deterministic)
        #pragma unroll
        for (int j = 0; j < 8; ++j) {
            s[j]  += __shfl_xor_sync(0xFFFFFFFF, s[j],  1);
            qq[j] += __shfl_xor_sync(0xFFFFFFFF, qq[j], 1);
            s[j]  += __shfl_xor_sync(0xFFFFFFFF, s[j],  4);
            qq[j] += __shfl_xor_sync(0xFFFFFFFF, qq[j], 4);
            s[j]  += __shfl_xor_sync(0xFFFFFFFF, s[j],  8);
            qq[j] += __shfl_xor_sync(0xFFFFFFFF, qq[j], 8);
            s[j]  += __shfl_xor_sync(0xFFFFFFFF, s[j],  16);
            qq[j] += __shfl_xor_sync(0xFFFFFFFF, qq[j], 16);
        }
        if (lane == 0 || lane == 2) {           // lane0: even groups, lane2: odd
            const int go = (lane == 0) ? 0 : 1;
            #pragma unroll
            for (int j = 0; j < 8; ++j)
                sW[wid * 16 + 2 * j + go] = make_float2(s[j], qq[j]);
        }
        __syncthreads();

        // ---- phase 2: finalize stats + h-direction pool combine ----
        const int tile = (n * HB_ + hb) * WB_ + wb;
        if (tid < 16) {
            float S = 0.f, Q = 0.f;
            #pragma unroll
            for (int w = 0; w < 8; ++w) {
                float2 v = sW[w * 16 + tid];
                S += v.x; Q += v.y;
            }
            g_ps[tile * G_ + tid] = S;
            g_pq[tile * G_ + tid] = Q;
        }

        #pragma unroll
        for (int i = 0; i < 4; ++i) {
            const int task = tid + (i << 8);
            const int oc = task & 63, win = (task >> 6) & 7, prl = task >> 9;
            const int pw = wb * 8 + win, pr = hb * 2 + prl;
            if (pw < OPW && pr < OPH) {
                const float* p = sPoolF + ((prl * 4) * 8 + win) * 72 + oc;
                float x0 = p[0], x1 = p[576], x2 = p[1152], x3 = p[1728];
                float ext = (sSg[oc] > 0.f)
                          ? fmaxf(fmaxf(x0, x1), fmaxf(x2, x3))
                          : fminf(fminf(x0, x1), fminf(x2, x3));
                g_ext[((size_t)(n * COUT + oc) * OPH + pr) * OPW + pw] = ext;
            }
        }
        __syncthreads();   // sPool/sW reused next tile; sX commit visible
    }
}

// ---------------------------------------------------------------------------
// Kernel 2: reduce per-tile partials -> mean, rsig. One warp per (n,g).
// ---------------------------------------------------------------------------
__global__ __launch_bounds__(256) void stats_reduce_kernel()
{
    const int wg   = (blockIdx.x * 256 + threadIdx.x) >> 5;
    const int lane = threadIdx.x & 31;
    if (wg >= N_ * G_) return;
    const int n = wg / G_, g = wg - n * G_;

    const int base = n * HB_ * WB_;
    float S = g_ps[(base + lane) * G_ + g] + g_ps[(base + 32 + lane) * G_ + g];
    float Q = g_pq[(base + lane) * G_ + g] + g_pq[(base + 32 + lane) * G_ + g];
    #pragma unroll
    for (int m = 16; m > 0; m >>= 1) {
        S += __shfl_xor_sync(0xFFFFFFFF, S, m);
        Q += __shfl_xor_sync(0xFFFFFFFF, Q, m);
    }
    if (lane == 0) {
        const float inv_cnt = 1.f / (float)(4 * OH * OW);
        float mean = S * inv_cnt;
        float var  = Q * inv_cnt - mean * mean;
        g_mean[wg] = mean;
        g_rsig[wg] = rsqrtf(var + 1e-5f);
    }
}

// ---------------------------------------------------------------------------
// Kernel 3: affine on pre-selected extreme, clamp. 4 px / thread (float4).
// ---------------------------------------------------------------------------
__global__ __launch_bounds__(256) void finalize_pool_kernel(
    const float* __restrict__ gnw,
    const float* __restrict__ gnb,
    const float* __restrict__ scale,
    float* __restrict__ out)
{
    const int total4 = (N_ * COUT * OPH * OPW) >> 2;
    int t4 = blockIdx.x * 256 + threadIdx.x;
    if (t4 >= total4) return;
    int idx = t4 << 2;

    float4 e = *(const float4*)(g_ext + idx);
    float r[4] = {e.x, e.y, e.z, e.w};
    float4 o;
    float* op = &o.x;

    #pragma unroll
    for (int i = 0; i < 4; ++i) {
        int id = idx + i;
        int t = id / (OPH * OPW);
        int c = t % COUT;
        int n = t / COUT;
        int gi = n * G_ + (c >> 2);
        float mean = g_mean[gi];
        float rsig = g_rsig[gi];
        float a = rsig * gnw[c] * scale[c];
        float b = (gnb[c] - mean * rsig * gnw[c]) * scale[c];
        op[i] = fminf(fmaxf(fmaf(r[i], a, b), 0.f), 1.f);
    }
    *(float4*)(out + idx) = o;
}

// ---------------------------------------------------------------------------
extern "C" void kernel_launch(void* const* d_in, const int* in_sizes, int n_in,
                              void* d_out, int out_size)
{
    const float* x     = (const float*)d_in[0];
    const float* cw    = (const float*)d_in[1];
    const float* cb    = (const float*)d_in[2];
    const float* gnw   = (const float*)d_in[3];
    const float* gnb   = (const float*)d_in[4];
    const float* scale = (const float*)d_in[5];
    float* out = (float*)d_out;

    static bool attr_set = false;
    if (!attr_set) {
        cudaFuncSetAttribute(conv_mma_kernel,
                             cudaFuncAttributeMaxDynamicSharedMemorySize, SMEM_TOTAL);
        attr_set = true;
    }

    bprep_kernel<<<6, 256>>>(cw, gnw, scale);

    dim3 grid(WB_, HB_ / 2, N_);
    conv_mma_kernel<<<grid, 256, SMEM_TOTAL>>>(x, cb);

    stats_reduce_kernel<<<(N_ * G_ * 32 + 255) / 256, 256>>>();

    const int total4 = (N_ * COUT * OPH * OPW) / 4;
    finalize_pool_kernel<<<(total4 + 255) / 256, 256>>>(gnw, gnb, scale, out);
}

// round 16
// speedup vs baseline: 1.8278x; 1.1117x over previous
#include <cuda_runtime.h>
#include <cuda_fp16.h>
#include <cstdint>
#include <cstddef>

#define N_    128
#define CIN   8
#define HIN   128
#define WIN   128
#define COUT  64
#define OH    126
#define OW    126
#define G_    16
#define OPH   31
#define OPW   31

#define HB_   16
#define WB_   4
#define NTILES (N_ * HB_ * WB_)

// ---- smem layout (bytes) — NO aliasing, double-buffered sX ----
#define OFF_B2   0        // 64*20*8   = 10240
#define OFF_X0   10240    // 9*10*36*4 = 12960 -> 23200
#define OFF_X1   23200    //            12960 -> 36160
#define OFF_POOL 36160    // 8*8*72*4  = 18432 -> 54592
#define OFF_SW   54592    // 8*16*8    = 1024  -> 55616
#define OFF_CB   55616    // 256
#define OFF_SG   55872    // 256
#define SMEM_TOTAL 56128

// ---- device scratch ----
__device__ uint2  g_B2h[64 * 20];
__device__ float  g_sgn[64];
__device__ float  g_ext[(size_t)N_ * COUT * OPH * OPW];
__device__ float  g_ps[NTILES * G_];
__device__ float  g_pq[NTILES * G_];
__device__ float2 g_ab[N_ * COUT];     // per (n,c) affine (a,b)

__device__ __forceinline__ uint32_t pack_h2(float lo, float hi) {
    uint32_t r;
    asm("cvt.rn.f16x2.f32 %0, %1, %2;" : "=r"(r) : "f"(hi), "f"(lo));
    return r;
}

__device__ __forceinline__ void mma16(float* c, const uint32_t* a, uint32_t b0, uint32_t b1) {
    asm volatile(
        "mma.sync.aligned.m16n8k16.row.col.f32.f16.f16.f32 "
        "{%0,%1,%2,%3}, {%4,%5,%6,%7}, {%8,%9}, {%0,%1,%2,%3};"
        : "+f"(c[0]), "+f"(c[1]), "+f"(c[2]), "+f"(c[3])
        : "r"(a[0]), "r"(a[1]), "r"(a[2]), "r"(a[3]), "r"(b0), "r"(b1));
}

__device__ __forceinline__ int koff(int k) {
    int ic = (k * 57) >> 9;
    int r  = k - 9 * ic;
    int kh = (r * 11) >> 5;
    int kw = r - 3 * kh;
    return ic * 360 + kh * 36 + kw;
}

__device__ __forceinline__ uint32_t smem_u32(const void* p) {
    uint32_t a;
    asm("{ .reg .u64 t; cvta.to.shared.u64 t, %1; cvt.u32.u64 %0, t; }" : "=r"(a) : "l"(p));
    return a;
}

#define CP_ASYNC16(dst, src, sz) \
    asm volatile("cp.async.ca.shared.global [%0], [%1], 16, %2;" \
                 :: "r"(dst), "l"(src), "r"(sz))
#define CP_COMMIT()  asm volatile("cp.async.commit_group;")
#define CP_WAIT(n)   asm volatile("cp.async.wait_group %0;" :: "n"(n))

// ---------------------------------------------------------------------------
// Kernel 0: weights -> fp16 pairs keyed [oc][kk][r4]; sign of a per oc.
// ---------------------------------------------------------------------------
__global__ void bprep_kernel(const float* __restrict__ cw,
                             const float* __restrict__ gnw,
                             const float* __restrict__ scale)
{
    int e = blockIdx.x * blockDim.x + threadIdx.x;
    if (e < 64) g_sgn[e] = (gnw[e] * scale[e] > 0.f) ? 1.f : -1.f;
    if (e >= 64 * 20) return;
    int oc = e / 20, rem = e - (e / 20) * 20;
    int kk = rem >> 2, r4 = rem & 3;
    int k0 = 16 * kk + 2 * r4;

    float w[4];
    #pragma unroll
    for (int i = 0; i < 4; ++i) {
        int k = k0 + ((i >> 1) << 3) + (i & 1);
        float v = 0.f;
        if (k < 72) {
            int ic = k / 9, r = k % 9;
            v = cw[((oc * 8 + ic) * 3 + r / 3) * 3 + (r % 3)];
        }
        w[i] = v;
    }
    __half2 p0 = __floats2half2_rn(w[0], w[1]);
    __half2 p1 = __floats2half2_rn(w[2], w[3]);
    uint2 out;
    out.x = *(uint32_t*)&p0;
    out.y = *(uint32_t*)&p1;
    g_B2h[e] = out;
}

// ---------------------------------------------------------------------------
// Kernel 1: implicit-GEMM conv (mma.sync fp16, f32 accum); register pool/stats
// epilogue; cp.async double-buffered input staging (2 h-tiles per block).
// 256 threads, grid (wb, hb2, n).
// ---------------------------------------------------------------------------
__global__ __launch_bounds__(256, 2)
void conv_mma_kernel(const float* __restrict__ x, const float* __restrict__ cb)
{
    extern __shared__ char smem[];
    uint2*  sB2    = (uint2*)(smem + OFF_B2);
    float*  sPoolF = (float*)(smem + OFF_POOL);   // [row8][win8][oc72]
    float2* sPool2 = (float2*)(smem + OFF_POOL);
    float2* sW     = (float2*)(smem + OFF_SW);    // [warp8][group16]
    float*  sCb    = (float*)(smem + OFF_CB);
    float*  sSg    = (float*)(smem + OFF_SG);

    const int tid  = threadIdx.x;
    const int wid  = tid >> 5;
    const int lane = tid & 31;
    const int wb = blockIdx.x, hb2 = blockIdx.y, n = blockIdx.z;
    const int w0 = wb * 32;

    const int q  = lane >> 2;
    const int r4 = lane & 3;

    // packed weights (640 float4), bias, signs
    {
        const float4* src = (const float4*)g_B2h;
        float4* dst = (float4*)sB2;
        #pragma unroll 3
        for (int i = tid; i < 640; i += 256) dst[i] = src[i];
    }
    if (tid < 64) { sCb[tid] = cb[tid]; sSg[tid] = g_sgn[tid]; }

    // per-thread staging coordinates (4 slots cover 810 float4 positions)
    int s_ic[4], s_hr[4], s_c4[4];
    #pragma unroll
    for (int i = 0; i < 4; ++i) {
        int idx = tid + (i << 8);
        s_ic[i] = idx / 90;
        int rem = idx - s_ic[i] * 90;
        s_hr[i] = rem / 9;
        s_c4[i] = rem - s_hr[i] * 9;
    }

    // ---- async stage BOTH tiles (double buffer) ----
    const uint32_t sX0u = smem_u32(smem + OFF_X0);
    const uint32_t sX1u = smem_u32(smem + OFF_X1);
    #pragma unroll
    for (int it = 0; it < 2; ++it) {
        const int h0 = (hb2 * 2 + it) * 8;
        const uint32_t sXu = it ? sX1u : sX0u;
        #pragma unroll
        for (int i = 0; i < 4; ++i) {
            int idx = tid + (i << 8);
            if (idx >= 810) break;
            int ic = s_ic[i], h = h0 + s_hr[i], gw = w0 + s_c4[i] * 4;
            bool ok = (ic < CIN) && (h < HIN) && (gw < WIN);
            const float* src = ok ? x + (((size_t)n * CIN + ic) * HIN + h) * WIN + gw : x;
            uint32_t dst = sXu + (uint32_t)(((ic * 10 + s_hr[i]) * 36 + s_c4[i] * 4) * 4);
            CP_ASYNC16(dst, src, ok ? 16 : 0);
        }
        CP_COMMIT();
    }
    CP_WAIT(1);          // tile 0 resident
    __syncthreads();

    const int P = wid * 36 + 4 * q;
    const int pxg = w0 + 4 * q;

    #pragma unroll
    for (int it = 0; it < 2; ++it) {
        const int hb = hb2 * 2 + it;
        const int h0 = hb * 8;
        const float* sX = (const float*)(smem + (it ? OFF_X1 : OFF_X0));

        if (it == 1) {
            CP_WAIT(0);       // tile 1 resident (own copies)
            __syncthreads();  // all threads' copies visible
        }

        // ---- MMA mainloop: 5 k16-steps ----
        float acc[2][8][4];
        #pragma unroll
        for (int t = 0; t < 2; ++t)
            #pragma unroll
            for (int j = 0; j < 8; ++j)
                #pragma unroll
                for (int u = 0; u < 4; ++u) acc[t][j][u] = 0.f;

        #pragma unroll
        for (int kk = 0; kk < 5; ++kk) {
            const int k0 = 16 * kk + 2 * r4;
            const float* p00 = sX + koff(k0)     + P;
            const float* p01 = sX + koff(k0 + 1) + P;
            const float* p10 = sX + koff(k0 + 8) + P;
            const float* p11 = sX + koff(k0 + 9) + P;

            uint32_t a[2][4];
            #pragma unroll
            for (int t = 0; t < 2; ++t) {
                const int c = 2 * t;
                a[t][0] = pack_h2(p00[c],     p01[c]);
                a[t][1] = pack_h2(p00[c + 1], p01[c + 1]);
                a[t][2] = pack_h2(p10[c],     p11[c]);
                a[t][3] = pack_h2(p10[c + 1], p11[c + 1]);
            }
            const uint2* bp = sB2 + q * 20 + kk * 4 + r4;
            #pragma unroll
            for (int j = 0; j < 8; ++j) {
                uint2 bv = bp[j * 160];
                mma16(acc[0][j], a[0], bv.x, bv.y);
                mma16(acc[1][j], a[1], bv.x, bv.y);
            }
        }

        // ---- phase 1: pool extremes + group partials from registers ----
        const bool hok = (h0 + wid) < OH;
        const bool c0 = hok && (pxg     < OW);
        const bool c1 = hok && (pxg + 1 < OW);
        const bool c2 = hok && (pxg + 2 < OW);
        const bool c3 = hok && (pxg + 3 < OW);
        float2* rowp = sPool2 + (wid * 8 + q) * 36;

        float s[8], qq[8];
        #pragma unroll
        for (int j = 0; j < 8; ++j) {
            const int oc = (j << 3) + (r4 << 1);
            float b0 = sCb[oc], b1 = sCb[oc + 1];
            float a00 = acc[0][j][0] + b0, a01 = acc[0][j][2] + b0;
            float a02 = acc[1][j][0] + b0, a03 = acc[1][j][2] + b0;
            float a10 = acc[0][j][1] + b1, a11 = acc[0][j][3] + b1;
            float a12 = acc[1][j][1] + b1, a13 = acc[1][j][3] + b1;

            float mx0 = fmaxf(fmaxf(a00, a01), fmaxf(a02, a03));
            float mn0 = fminf(fminf(a00, a01), fminf(a02, a03));
            float mx1 = fmaxf(fmaxf(a10, a11), fmaxf(a12, a13));
            float mn1 = fminf(fminf(a10, a11), fminf(a12, a13));
            float e0 = (sSg[oc]     > 0.f) ? mx0 : mn0;
            float e1 = (sSg[oc + 1] > 0.f) ? mx1 : mn1;
            rowp[(j << 2) + r4] = make_float2(e0, e1);

            float v00 = c0 ? a00 : 0.f, v01 = c1 ? a01 : 0.f;
            float v02 = c2 ? a02 : 0.f, v03 = c3 ? a03 : 0.f;
            float v10 = c0 ? a10 : 0.f, v11 = c1 ? a11 : 0.f;
            float v12 = c2 ? a12 : 0.f, v13 = c3 ? a13 : 0.f;
            s[j] = ((v00 + v01) + (v02 + v03)) + ((v10 + v11) + (v12 + v13));
            qq[j] = fmaf(v00, v00, fmaf(v01, v01, fmaf(v02, v02, fmaf(v03, v03,
                    fmaf(v10, v10, fmaf(v11, v11, fmaf(v12, v12, v13 * v13)))))));
        }

        // warp shuffle reduce over coset {1,4,8,16} (fixed tree, deterministic)
        #pragma unroll
        for (int j = 0; j < 8; ++j) {
            s[j]  += __shfl_xor_sync(0xFFFFFFFF, s[j],  1);
            qq[j] += __shfl_xor_sync(0xFFFFFFFF, qq[j], 1);
            s[j]  += __shfl_xor_sync(0xFFFFFFFF, s[j],  4);
            qq[j] += __shfl_xor_sync(0xFFFFFFFF, qq[j], 4);
            s[j]  += __shfl_xor_sync(0xFFFFFFFF, s[j],  8);
            qq[j] += __shfl_xor_sync(0xFFFFFFFF, qq[j], 8);
            s[j]  += __shfl_xor_sync(0xFFFFFFFF, s[j],  16);
            qq[j] += __shfl_xor_sync(0xFFFFFFFF, qq[j], 16);
        }
        if (lane == 0 || lane == 2) {
            const int go = (lane == 0) ? 0 : 1;
            #pragma unroll
            for (int j = 0; j < 8; ++j)
                sW[wid * 16 + 2 * j + go] = make_float2(s[j], qq[j]);
        }
        __syncthreads();

        // ---- phase 2: finalize stats + h-direction pool combine ----
        const int tile = (n * HB_ + hb) * WB_ + wb;
        if (tid < 16) {
            float S = 0.f, Q = 0.f;
            #pragma unroll
            for (int w = 0; w < 8; ++w) {
                float2 v = sW[w * 16 + tid];
                S += v.x; Q += v.y;
            }
            g_ps[tile * G_ + tid] = S;
            g_pq[tile * G_ + tid] = Q;
        }

        #pragma unroll
        for (int i = 0; i < 4; ++i) {
            const int task = tid + (i << 8);
            const int oc = task & 63, win = (task >> 6) & 7, prl = task >> 9;
            const int pw = wb * 8 + win, pr = hb * 2 + prl;
            if (pw < OPW && pr < OPH) {
                const float* p = sPoolF + ((prl * 4) * 8 + win) * 72 + oc;
                float x0 = p[0], x1 = p[576], x2 = p[1152], x3 = p[1728];
                float ext = (sSg[oc] > 0.f)
                          ? fmaxf(fmaxf(x0, x1), fmaxf(x2, x3))
                          : fminf(fminf(x0, x1), fminf(x2, x3));
                g_ext[((size_t)(n * COUT + oc) * OPH + pr) * OPW + pw] = ext;
            }
        }
        __syncthreads();   // sPool/sW reused by next tile
    }
}

// ---------------------------------------------------------------------------
// Kernel 2: reduce per-tile partials -> per-(n,c) affine (a,b) table.
// One warp per (n,g), fixed shuffle tree (deterministic).
// ---------------------------------------------------------------------------
__global__ __launch_bounds__(256) void stats_reduce_kernel(
    const float* __restrict__ gnw,
    const float* __restrict__ gnb,
    const float* __restrict__ scale)
{
    const int wg   = (blockIdx.x * 256 + threadIdx.x) >> 5;
    const int lane = threadIdx.x & 31;
    if (wg >= N_ * G_) return;
    const int n = wg / G_, g = wg - n * G_;

    const int base = n * HB_ * WB_;
    float S = g_ps[(base + lane) * G_ + g] + g_ps[(base + 32 + lane) * G_ + g];
    float Q = g_pq[(base + lane) * G_ + g] + g_pq[(base + 32 + lane) * G_ + g];
    #pragma unroll
    for (int m = 16; m > 0; m >>= 1) {
        S += __shfl_xor_sync(0xFFFFFFFF, S, m);
        Q += __shfl_xor_sync(0xFFFFFFFF, Q, m);
    }
    if (lane == 0) {
        const float inv_cnt = 1.f / (float)(4 * OH * OW);
        float mean = S * inv_cnt;
        float var  = Q * inv_cnt - mean * mean;
        float rsig = rsqrtf(var + 1e-5f);
        #pragma unroll
        for (int i = 0; i < 4; ++i) {
            int c = g * 4 + i;
            float a = rsig * gnw[c] * scale[c];
            float b = (gnb[c] - mean * rsig * gnw[c]) * scale[c];
            g_ab[n * COUT + c] = make_float2(a, b);
        }
    }
}

// ---------------------------------------------------------------------------
// Kernel 3: affine (from table) on pre-selected extreme, clamp. float4 I/O.
// ---------------------------------------------------------------------------
__global__ __launch_bounds__(256) void finalize_pool_kernel(float* __restrict__ out)
{
    const int total4 = (N_ * COUT * OPH * OPW) >> 2;
    int t4 = blockIdx.x * 256 + threadIdx.x;
    if (t4 >= total4) return;
    int idx = t4 << 2;

    float4 e = *(const float4*)(g_ext + idx);
    float r[4] = {e.x, e.y, e.z, e.w};
    float4 o;
    float* op = &o.x;

    #pragma unroll
    for (int i = 0; i < 4; ++i) {
        int nc = (idx + i) / (OPH * OPW);
        float2 ab = g_ab[nc];
        op[i] = fminf(fmaxf(fmaf(r[i], ab.x, ab.y), 0.f), 1.f);
    }
    *(float4*)(out + idx) = o;
}

// ---------------------------------------------------------------------------
extern "C" void kernel_launch(void* const* d_in, const int* in_sizes, int n_in,
                              void* d_out, int out_size)
{
    const float* x     = (const float*)d_in[0];
    const float* cw    = (const float*)d_in[1];
    const float* cb    = (const float*)d_in[2];
    const float* gnw   = (const float*)d_in[3];
    const float* gnb   = (const float*)d_in[4];
    const float* scale = (const float*)d_in[5];
    float* out = (float*)d_out;

    static bool attr_set = false;
    if (!attr_set) {
        cudaFuncSetAttribute(conv_mma_kernel,
                             cudaFuncAttributeMaxDynamicSharedMemorySize, SMEM_TOTAL);
        attr_set = true;
    }

    bprep_kernel<<<6, 256>>>(cw, gnw, scale);

    dim3 grid(WB_, HB_ / 2, N_);
    conv_mma_kernel<<<grid, 256, SMEM_TOTAL>>>(x, cb);

    stats_reduce_kernel<<<(N_ * G_ * 32 + 255) / 256, 256>>>(gnw, gnb, scale);

    const int total4 = (N_ * COUT * OPH * OPW) / 4;
    finalize_pool_kernel<<<(total4 + 255) / 256, 256>>>(out);
}